// round 10
// baseline (speedup 1.0000x reference)
#include <cuda_runtime.h>
#include <math.h>
#include <float.h>

#define B_ROWS 256
#define N_COLS 65536
#define SPLIT  4
#define CHUNK  (N_COLS / SPLIT)        // 16384 elements per CTA
#define T1     256                     // threads per CTA
#define NCHUNK (B_ROWS * SPLIT)        // 1024 CTAs
#define CAP    256                     // candidate buffer per row
#define THRESH 0.998f                  // negative top-10 prefilter

// Scratch (static device globals; no runtime allocation)
__device__ float g_sum_p[NCHUNK];
__device__ int   g_nneg[NCHUNK];
__device__ int   g_cnt[B_ROWS];        // zero-init; reset by elected CTA each replay
__device__ float g_cand[B_ROWS * CAP];
__device__ int   g_done;               // zero-init; reset by elected CTA each replay

__device__ __forceinline__ float warpSumf(float v) {
#pragma unroll
    for (int o = 16; o > 0; o >>= 1)
        v += __shfl_xor_sync(0xffffffffu, v, o);
    return v;
}
__device__ __forceinline__ int warpSumi(int v) {
#pragma unroll
    for (int o = 16; o > 0; o >>= 1)
        v += __shfl_xor_sync(0xffffffffu, v, o);
    return v;
}

// exp2 argument for positives: 92.33248*(0.8-sc)^2 expanded as quadratic in sc
// (92.33248 = 64*log2(e), so exp2(t) == exp(64*(0.8-sc)^2))
#define C_A  92.33248261689366f
#define C_B -147.73197218702986f
#define C_C  59.09278887481146f

__device__ __forceinline__ void process_elem(
    float s_, float l_,
    float& sum_p, float& s_min, float s_th,
    int& nneg, int* cnt_ptr, float* cand_ptr)
{
    // ---- positives: predicated exp with adaptive cutoff ----
    bool pos  = (l_ > 0.5f);
    bool keep = pos && (s_ < s_th);
    float sc = fminf(s_, 0.8f);
    float u  = fmaf(sc, C_A, C_B);
    float t  = fmaf(u, sc, C_C);            // = 92.332*(0.8-sc)^2
    if (keep) {
        sum_p += exp2f(t);                  // MUFU only when kept
        s_min  = fminf(s_min, s_);
    }

    // ---- negatives: count + rare candidate push (no per-elem top-10) ----
    bool neg = (l_ < 0.25f);
    nneg += neg;
    if (neg && (s_ > THRESH)) {             // ~1 hit per warp per kernel
        int idx = atomicAdd(cnt_ptr, 1);
        if (idx < CAP) cand_ptr[idx] = s_;
    }
}

// Sorted-ascending top-10 insert bubble
__device__ __forceinline__ void top10_insert(float (&top)[10], float v) {
    if (v > top[0]) {
#pragma unroll
        for (int k = 0; k < 9; k++) {
            float hi = fmaxf(v, top[k]);
            top[k] = fminf(hi, top[k + 1]);
        }
        top[9] = fmaxf(v, top[9]);
    }
}

__global__ __launch_bounds__(T1, 4)      // reg cap 64: room for 8 float4 in flight
void ranking_fused(const float* __restrict__ sim,
                   const float* __restrict__ lab,
                   float* __restrict__ out)
{
    const int chunk = blockIdx.x;
    const int row   = chunk >> 2;           // SPLIT = 4
    const int part  = chunk & 3;
    const int tid   = threadIdx.x;
    const int lane  = tid & 31;
    const int wid   = tid >> 5;

    const size_t base = (size_t)row * N_COLS + (size_t)part * CHUNK;
    const float4* s4 = reinterpret_cast<const float4*>(sim + base);
    const float4* l4 = reinterpret_cast<const float4*>(lab + base);

    int*   cnt_ptr  = &g_cnt[row];
    float* cand_ptr = &g_cand[row * CAP];

    float sum_p = 0.0f;
    float s_min = FLT_MAX;
    float s_th  = FLT_MAX;
    int   nneg  = 0;

    // CHUNK/4 = 4096 float4s, 256 threads -> 16 float4 per thread.
    // 4 groups; each group: 8 independent float4 loads issued up-front (MLP=8),
    // then 16 elements processed; threshold refresh between groups.
#pragma unroll 1
    for (int g = 0; g < 4; g++) {
        float4 sv[4], lv[4];
#pragma unroll
        for (int j = 0; j < 4; j++) {
            int i = tid + (g * 4 + j) * T1;
            sv[j] = s4[i];
            lv[j] = l4[i];
        }
#pragma unroll
        for (int j = 0; j < 4; j++) {
            process_elem(sv[j].x, lv[j].x, sum_p, s_min, s_th, nneg, cnt_ptr, cand_ptr);
            process_elem(sv[j].y, lv[j].y, sum_p, s_min, s_th, nneg, cnt_ptr, cand_ptr);
            process_elem(sv[j].z, lv[j].z, sum_p, s_min, s_th, nneg, cnt_ptr, cand_ptr);
            process_elem(sv[j].w, lv[j].w, sum_p, s_min, s_th, nneg, cnt_ptr, cand_ptr);
        }
        // keep logit >= local_max_logit - 16:
        // max = 64*dmin^2 ; keep s <= 0.8 - sqrt(dmin^2 - 0.25)
        float dmin = 0.8f - s_min;
        s_th = (dmin <= 0.500001f) ? FLT_MAX
                                   : (0.8f - sqrtf(fmaf(dmin, dmin, -0.25f)));
    }

    // ---- block reduction of sum_p / nneg, publish chunk partials ----
    __shared__ float sh_p[T1 / 32];
    __shared__ int   sh_n[T1 / 32];
    __shared__ int   sh_elect;
    float wp = warpSumf(sum_p);
    int   wn = warpSumi(nneg);
    if (lane == 0) { sh_p[wid] = wp; sh_n[wid] = wn; }
    __syncthreads();
    if (tid < 32) {
        float p = (tid < T1 / 32) ? sh_p[tid] : 0.0f;
        int   n = (tid < T1 / 32) ? sh_n[tid] : 0;
        p = warpSumf(p);
        n = warpSumi(n);
        if (tid == 0) { g_sum_p[chunk] = p; g_nneg[chunk] = n; }
    }

    // ---- last-CTA election ----
    __threadfence();                        // order partials + candidate pushes
    __syncthreads();
    if (tid == 0)
        sh_elect = (atomicAdd(&g_done, 1) == (NCHUNK - 1)) ? 1 : 0;
    __syncthreads();
    if (!sh_elect) return;

    // =========== elected CTA: finisher (one row per thread) ===========
    __threadfence();                        // acquire all other CTAs' writes
    {
        const int r = tid;                  // T1 == B_ROWS
        float sp = 0.0f; int nn = 0;
#pragma unroll
        for (int c = 0; c < SPLIT; c++) {
            sp += g_sum_p[r * SPLIT + c];
            nn += g_nneg[r * SPLIT + c];
        }
        int cnt = g_cnt[r];
        g_cnt[r] = 0;                       // reset for next graph replay

        float lse_n;
        if (nn > 20 && cnt >= 10 && cnt <= CAP) {
            // fast path: exact top-10 from candidate multiset (order-invariant).
            // 8-wide batched prefetch -> MLP=8 instead of latency-serial scan.
            float top[10];
#pragma unroll
            for (int k = 0; k < 10; k++) top[k] = -FLT_MAX;
            const float* cp = &g_cand[r * CAP];
#pragma unroll 1
            for (int b = 0; b < cnt; b += 8) {
                float v[8];
#pragma unroll
                for (int k = 0; k < 8; k++)
                    v[k] = (b + k < cnt) ? cp[b + k] : -FLT_MAX;
#pragma unroll
                for (int k = 0; k < 8; k++)
                    top10_insert(top, v[k]);
            }
            float sum_top = 0.0f;
#pragma unroll
            for (int k = 0; k < 10; k++) {
                float e = fmaxf(top[k] - 0.2f, 0.0f);
                sum_top += __expf(64.0f * e * e);
            }
            lse_n = logf(sum_top);
        } else if (nn > 0) {
            // exact fallback (never taken on this data): serial row scan
            const float* ss = sim + (size_t)r * N_COLS;
            const float* ll = lab + (size_t)r * N_COLS;
            float sum_n = 0.0f;
            float top[10];
#pragma unroll
            for (int k = 0; k < 10; k++) top[k] = -FLT_MAX;
            for (int i = 0; i < N_COLS; i++) {
                if (ll[i] < 0.25f) {
                    float s_ = ss[i];
                    float e = fmaxf(s_ - 0.2f, 0.0f);
                    sum_n += __expf(64.0f * e * e);
                    top10_insert(top, s_);
                }
            }
            if (nn > 20) {
                float sum_top = 0.0f;
#pragma unroll
                for (int k = 0; k < 10; k++) {
                    float e = fmaxf(top[k] - 0.2f, 0.0f);
                    sum_top += __expf(64.0f * e * e);
                }
                lse_n = logf(sum_top);
            } else {
                lse_n = logf(sum_n);
            }
        } else {
            lse_n = -FLT_MAX;               // no negatives: acts as -inf
        }

        float lse_p = (sp > 0.0f) ? logf(sp) : 0.0f;

        float x = lse_n + lse_p;
        float sploss;
        if (x > 0.0f) sploss = x + log1pf(expf(-x));
        else          sploss = log1pf(expf(x));

        // deterministic block-tree mean over 256 rows
        __shared__ float shf[B_ROWS / 32];
        float v = warpSumf(sploss);
        if (lane == 0) shf[wid] = v;
        __syncthreads();
        if (tid < 32) {
            float w = (tid < B_ROWS / 32) ? shf[tid] : 0.0f;
            w = warpSumf(w);
            if (tid == 0) {
                out[0] = w * (1.0f / (float)B_ROWS);
                g_done = 0;                 // reset for next graph replay
            }
        }
    }
}

extern "C" void kernel_launch(void* const* d_in, const int* in_sizes, int n_in,
                              void* d_out, int out_size)
{
    const float* sim = (const float*)d_in[0];
    const float* lab = (const float*)d_in[1];
    float* out = (float*)d_out;

    ranking_fused<<<NCHUNK, T1>>>(sim, lab, out);
}

// round 12
// speedup vs baseline: 1.3476x; 1.3476x over previous
#include <cuda_runtime.h>
#include <math.h>
#include <float.h>

#define B_ROWS 256
#define N_COLS 65536
#define SPLIT  4
#define CHUNK  (N_COLS / SPLIT)        // 16384 elements per CTA
#define T1     256                     // threads per CTA
#define NCHUNK (B_ROWS * SPLIT)        // 1024 CTAs  (<= 7/SM * 148 = 1036 slots)
#define CAP    256                     // candidate buffer per row
#define THRESH 0.998f                  // negative top-10 prefilter

// Scratch (static device globals; no runtime allocation)
__device__ float g_sum_p[NCHUNK];
__device__ int   g_nneg[NCHUNK];
__device__ int   g_cnt[B_ROWS];        // zero-init; reset by elected CTA each replay
__device__ float g_cand[B_ROWS * CAP];
__device__ int   g_done;               // zero-init; reset by elected CTA each replay

__device__ __forceinline__ float warpSumf(float v) {
#pragma unroll
    for (int o = 16; o > 0; o >>= 1)
        v += __shfl_xor_sync(0xffffffffu, v, o);
    return v;
}
__device__ __forceinline__ int warpSumi(int v) {
#pragma unroll
    for (int o = 16; o > 0; o >>= 1)
        v += __shfl_xor_sync(0xffffffffu, v, o);
    return v;
}

// exp2 argument for positives: 92.33248*(0.8-sc)^2 expanded as quadratic in sc
// (92.33248 = 64*log2(e), so exp2(t) == exp(64*(0.8-sc)^2))
#define C_A  92.33248261689366f
#define C_B -147.73197218702986f
#define C_C  59.09278887481146f

__device__ __forceinline__ void process_elem(
    float s_, float l_,
    float& sum_p, float& s_min, float s_th,
    int& nneg, int* cnt_ptr, float* cand_ptr)
{
    // ---- positives: predicated exp with adaptive cutoff ----
    bool pos  = (l_ > 0.5f);
    bool keep = pos && (s_ < s_th);
    float sc = fminf(s_, 0.8f);
    float u  = fmaf(sc, C_A, C_B);
    float t  = fmaf(u, sc, C_C);            // = 92.332*(0.8-sc)^2
    if (keep) {
        sum_p += exp2f(t);                  // MUFU only when kept
        s_min  = fminf(s_min, s_);
    }

    // ---- negatives: count + rare candidate push (no per-elem top-10) ----
    bool neg = (l_ < 0.25f);
    nneg += neg;
    if (neg && (s_ > THRESH)) {             // ~1 hit per warp per kernel
        int idx = atomicAdd(cnt_ptr, 1);
        if (idx < CAP) cand_ptr[idx] = s_;
    }
}

// Sorted-ascending top-10 insert bubble
__device__ __forceinline__ void top10_insert(float (&top)[10], float v) {
    if (v > top[0]) {
#pragma unroll
        for (int k = 0; k < 9; k++) {
            float hi = fmaxf(v, top[k]);
            top[k] = fminf(hi, top[k + 1]);
        }
        top[9] = fmaxf(v, top[9]);
    }
}

// 7 CTAs/SM -> 36-reg cap -> 1036 resident CTAs: grid 1024 runs in ONE wave,
// and 2 float4-pairs (16 data regs) of MLP fit the budget without spills.
__global__ __launch_bounds__(T1, 7)
void ranking_fused(const float* __restrict__ sim,
                   const float* __restrict__ lab,
                   float* __restrict__ out)
{
    const int chunk = blockIdx.x;
    const int row   = chunk >> 2;           // SPLIT = 4
    const int part  = chunk & 3;
    const int tid   = threadIdx.x;
    const int lane  = tid & 31;
    const int wid   = tid >> 5;

    const size_t base = (size_t)row * N_COLS + (size_t)part * CHUNK;
    const float4* s4 = reinterpret_cast<const float4*>(sim + base);
    const float4* l4 = reinterpret_cast<const float4*>(lab + base);

    int*   cnt_ptr  = &g_cnt[row];
    float* cand_ptr = &g_cand[row * CAP];

    float sum_p = 0.0f;
    float s_min = FLT_MAX;
    float s_th  = FLT_MAX;
    int   nneg  = 0;

    // 16 float4/thread: 4 groups x (2 steps of 2 float4-pairs).
    // Each step issues 4 independent LDG.128 (2 sim + 2 lab) before any use.
#pragma unroll 1
    for (int g = 0; g < 4; g++) {
#pragma unroll
        for (int u = 0; u < 2; u++) {
            int i = tid + (g * 2 + u) * 2 * T1;
            float4 s0 = s4[i];
            float4 l0 = l4[i];
            float4 s1 = s4[i + T1];
            float4 l1 = l4[i + T1];
            process_elem(s0.x, l0.x, sum_p, s_min, s_th, nneg, cnt_ptr, cand_ptr);
            process_elem(s0.y, l0.y, sum_p, s_min, s_th, nneg, cnt_ptr, cand_ptr);
            process_elem(s0.z, l0.z, sum_p, s_min, s_th, nneg, cnt_ptr, cand_ptr);
            process_elem(s0.w, l0.w, sum_p, s_min, s_th, nneg, cnt_ptr, cand_ptr);
            process_elem(s1.x, l1.x, sum_p, s_min, s_th, nneg, cnt_ptr, cand_ptr);
            process_elem(s1.y, l1.y, sum_p, s_min, s_th, nneg, cnt_ptr, cand_ptr);
            process_elem(s1.z, l1.z, sum_p, s_min, s_th, nneg, cnt_ptr, cand_ptr);
            process_elem(s1.w, l1.w, sum_p, s_min, s_th, nneg, cnt_ptr, cand_ptr);
        }
        // keep logit >= local_max_logit - 16:
        // max = 64*dmin^2 ; keep s <= 0.8 - sqrt(dmin^2 - 0.25)
        float dmin = 0.8f - s_min;
        s_th = (dmin <= 0.500001f) ? FLT_MAX
                                   : (0.8f - sqrtf(fmaf(dmin, dmin, -0.25f)));
    }

    // ---- block reduction of sum_p / nneg, publish chunk partials ----
    __shared__ float sh_p[T1 / 32];
    __shared__ int   sh_n[T1 / 32];
    __shared__ int   sh_elect;
    float wp = warpSumf(sum_p);
    int   wn = warpSumi(nneg);
    if (lane == 0) { sh_p[wid] = wp; sh_n[wid] = wn; }
    __syncthreads();
    if (tid < 32) {
        float p = (tid < T1 / 32) ? sh_p[tid] : 0.0f;
        int   n = (tid < T1 / 32) ? sh_n[tid] : 0;
        p = warpSumf(p);
        n = warpSumi(n);
        if (tid == 0) { g_sum_p[chunk] = p; g_nneg[chunk] = n; }
    }

    // ---- last-CTA election ----
    __threadfence();                        // order partials + candidate pushes
    __syncthreads();
    if (tid == 0)
        sh_elect = (atomicAdd(&g_done, 1) == (NCHUNK - 1)) ? 1 : 0;
    __syncthreads();
    if (!sh_elect) return;

    // =========== elected CTA: finisher (one row per thread) ===========
    __threadfence();                        // acquire all other CTAs' writes
    {
        const int r = tid;                  // T1 == B_ROWS
        float sp = 0.0f; int nn = 0;
#pragma unroll
        for (int c = 0; c < SPLIT; c++) {
            sp += g_sum_p[r * SPLIT + c];
            nn += g_nneg[r * SPLIT + c];
        }
        int cnt = g_cnt[r];
        g_cnt[r] = 0;                       // reset for next graph replay

        float lse_n;
        if (nn > 20 && cnt >= 10 && cnt <= CAP) {
            // fast path: exact top-10 from candidate multiset (order-invariant).
            // 4-wide batched prefetch -> MLP=4 instead of latency-serial scan.
            float top[10];
#pragma unroll
            for (int k = 0; k < 10; k++) top[k] = -FLT_MAX;
            const float* cp = &g_cand[r * CAP];
#pragma unroll 1
            for (int b = 0; b < cnt; b += 4) {
                float v[4];
#pragma unroll
                for (int k = 0; k < 4; k++)
                    v[k] = (b + k < cnt) ? cp[b + k] : -FLT_MAX;
#pragma unroll
                for (int k = 0; k < 4; k++)
                    top10_insert(top, v[k]);
            }
            float sum_top = 0.0f;
#pragma unroll
            for (int k = 0; k < 10; k++) {
                float e = fmaxf(top[k] - 0.2f, 0.0f);
                sum_top += __expf(64.0f * e * e);
            }
            lse_n = logf(sum_top);
        } else if (nn > 0) {
            // exact fallback (never taken on this data): serial row scan
            const float* ss = sim + (size_t)r * N_COLS;
            const float* ll = lab + (size_t)r * N_COLS;
            float sum_n = 0.0f;
            float top[10];
#pragma unroll
            for (int k = 0; k < 10; k++) top[k] = -FLT_MAX;
            for (int i = 0; i < N_COLS; i++) {
                if (ll[i] < 0.25f) {
                    float s_ = ss[i];
                    float e = fmaxf(s_ - 0.2f, 0.0f);
                    sum_n += __expf(64.0f * e * e);
                    top10_insert(top, s_);
                }
            }
            if (nn > 20) {
                float sum_top = 0.0f;
#pragma unroll
                for (int k = 0; k < 10; k++) {
                    float e = fmaxf(top[k] - 0.2f, 0.0f);
                    sum_top += __expf(64.0f * e * e);
                }
                lse_n = logf(sum_top);
            } else {
                lse_n = logf(sum_n);
            }
        } else {
            lse_n = -FLT_MAX;               // no negatives: acts as -inf
        }

        float lse_p = (sp > 0.0f) ? logf(sp) : 0.0f;

        float x = lse_n + lse_p;
        float sploss;
        if (x > 0.0f) sploss = x + log1pf(expf(-x));
        else          sploss = log1pf(expf(x));

        // deterministic block-tree mean over 256 rows
        __shared__ float shf[B_ROWS / 32];
        float v = warpSumf(sploss);
        if (lane == 0) shf[wid] = v;
        __syncthreads();
        if (tid < 32) {
            float w = (tid < B_ROWS / 32) ? shf[tid] : 0.0f;
            w = warpSumf(w);
            if (tid == 0) {
                out[0] = w * (1.0f / (float)B_ROWS);
                g_done = 0;                 // reset for next graph replay
            }
        }
    }
}

extern "C" void kernel_launch(void* const* d_in, const int* in_sizes, int n_in,
                              void* d_out, int out_size)
{
    const float* sim = (const float*)d_in[0];
    const float* lab = (const float*)d_in[1];
    float* out = (float*)d_out;

    ranking_fused<<<NCHUNK, T1>>>(sim, lab, out);
}

// round 14
// speedup vs baseline: 1.4284x; 1.0600x over previous
#include <cuda_runtime.h>
#include <math.h>
#include <float.h>

#define B_ROWS 256
#define N_COLS 65536
#define SPLIT  4
#define CHUNK  (N_COLS / SPLIT)        // 16384 elements per CTA
#define T1     256                     // threads per CTA
#define NCHUNK (B_ROWS * SPLIT)        // 1024 CTAs
#define CAP    256                     // candidate buffer per row
#define THRESH 0.998f                  // negative top-10 prefilter

// Scratch (static device globals; no runtime allocation)
__device__ float g_sum_p[NCHUNK];
__device__ int   g_nneg[NCHUNK];
__device__ int   g_cnt[B_ROWS];        // zero-init; reset by elected CTA each replay
__device__ float g_cand[B_ROWS * CAP];
__device__ int   g_done;               // zero-init; reset by elected CTA each replay

__device__ __forceinline__ float warpSumf(float v) {
#pragma unroll
    for (int o = 16; o > 0; o >>= 1)
        v += __shfl_xor_sync(0xffffffffu, v, o);
    return v;
}
__device__ __forceinline__ int warpSumi(int v) {
#pragma unroll
    for (int o = 16; o > 0; o >>= 1)
        v += __shfl_xor_sync(0xffffffffu, v, o);
    return v;
}

// exp2 argument for positives: 92.33248*(0.8-sc)^2 expanded as quadratic in sc
// (92.33248 = 64*log2(e), so exp2(t) == exp(64*(0.8-sc)^2))
#define C_A  92.33248261689366f
#define C_B -147.73197218702986f
#define C_C  59.09278887481146f

__device__ __forceinline__ void process_elem(
    float s_, float l_,
    float& sum_p, float& s_min, float s_th,
    int& nneg, int* cnt_ptr, float* cand_ptr)
{
    // ---- positives: predicated exp with adaptive cutoff ----
    bool pos  = (l_ > 0.5f);
    bool keep = pos && (s_ < s_th);
    float sc = fminf(s_, 0.8f);
    float u  = fmaf(sc, C_A, C_B);
    float t  = fmaf(u, sc, C_C);            // = 92.332*(0.8-sc)^2
    if (keep) {
        sum_p += exp2f(t);                  // MUFU only when kept
        s_min  = fminf(s_min, s_);
    }

    // ---- negatives: count + rare candidate push (no per-elem top-10) ----
    bool neg = (l_ < 0.25f);
    nneg += neg;
    if (neg && (s_ > THRESH)) {             // ~1 hit per warp per kernel
        int idx = atomicAdd(cnt_ptr, 1);
        if (idx < CAP) cand_ptr[idx] = s_;
    }
}

// Sorted-ascending top-10 insert bubble
__device__ __forceinline__ void top10_insert(float (&top)[10], float v) {
    if (v > top[0]) {
#pragma unroll
        for (int k = 0; k < 9; k++) {
            float hi = fmaxf(v, top[k]);
            top[k] = fminf(hi, top[k + 1]);
        }
        top[9] = fmaxf(v, top[9]);
    }
}

__global__ __launch_bounds__(T1)
void ranking_fused(const float* __restrict__ sim,
                   const float* __restrict__ lab,
                   float* __restrict__ out)
{
    const int chunk = blockIdx.x;
    const int row   = chunk >> 2;           // SPLIT = 4
    const int part  = chunk & 3;
    const int tid   = threadIdx.x;
    const int lane  = tid & 31;
    const int wid   = tid >> 5;

    const size_t base = (size_t)row * N_COLS + (size_t)part * CHUNK;
    const float4* s4 = reinterpret_cast<const float4*>(sim + base);
    const float4* l4 = reinterpret_cast<const float4*>(lab + base);

    int*   cnt_ptr  = &g_cnt[row];
    float* cand_ptr = &g_cand[row * CAP];

    float sum_p = 0.0f;
    float s_min = FLT_MAX;
    float s_th  = FLT_MAX;
    int   nneg  = 0;

    // CHUNK/4 = 4096 float4s, 256 threads -> 16 float4 per thread.
    // 4 groups of 4 float4 (round-9 proven-best shape: let ptxas schedule),
    // threshold refresh between groups.
#pragma unroll 1
    for (int g = 0; g < 4; g++) {
#pragma unroll
        for (int j = 0; j < 4; j++) {
            int i = tid + (g * 4 + j) * T1;
            float4 s = s4[i];
            float4 l = l4[i];
            process_elem(s.x, l.x, sum_p, s_min, s_th, nneg, cnt_ptr, cand_ptr);
            process_elem(s.y, l.y, sum_p, s_min, s_th, nneg, cnt_ptr, cand_ptr);
            process_elem(s.z, l.z, sum_p, s_min, s_th, nneg, cnt_ptr, cand_ptr);
            process_elem(s.w, l.w, sum_p, s_min, s_th, nneg, cnt_ptr, cand_ptr);
        }
        // keep logit >= local_max_logit - 16:
        // max = 64*dmin^2 ; keep s <= 0.8 - sqrt(dmin^2 - 0.25)
        float dmin = 0.8f - s_min;
        s_th = (dmin <= 0.500001f) ? FLT_MAX
                                   : (0.8f - sqrtf(fmaf(dmin, dmin, -0.25f)));
    }

    // ---- block reduction of sum_p / nneg, publish chunk partials ----
    __shared__ float sh_p[T1 / 32];
    __shared__ int   sh_n[T1 / 32];
    __shared__ int   sh_elect;
    float wp = warpSumf(sum_p);
    int   wn = warpSumi(nneg);
    if (lane == 0) { sh_p[wid] = wp; sh_n[wid] = wn; }
    __syncthreads();
    if (tid < 32) {
        float p = (tid < T1 / 32) ? sh_p[tid] : 0.0f;
        int   n = (tid < T1 / 32) ? sh_n[tid] : 0;
        p = warpSumf(p);
        n = warpSumi(n);
        if (tid == 0) { g_sum_p[chunk] = p; g_nneg[chunk] = n; }
    }

    // ---- last-CTA election ----
    __threadfence();                        // order partials + candidate pushes
    __syncthreads();
    if (tid == 0)
        sh_elect = (atomicAdd(&g_done, 1) == (NCHUNK - 1)) ? 1 : 0;
    __syncthreads();
    if (!sh_elect) return;

    // =========== elected CTA: finisher (one row per thread) ===========
    __threadfence();                        // acquire all other CTAs' writes
    {
        const int r = tid;                  // T1 == B_ROWS
        float sp = 0.0f; int nn = 0;
#pragma unroll
        for (int c = 0; c < SPLIT; c++) {
            sp += g_sum_p[r * SPLIT + c];
            nn += g_nneg[r * SPLIT + c];
        }
        int cnt = g_cnt[r];
        g_cnt[r] = 0;                       // reset for next graph replay

        float lse_n;
        if (nn > 20 && cnt >= 10 && cnt <= CAP) {
            // fast path: exact top-10 from candidate multiset (order-invariant).
            // 4-wide batched prefetch -> MLP=4 instead of latency-serial scan.
            float top[10];
#pragma unroll
            for (int k = 0; k < 10; k++) top[k] = -FLT_MAX;
            const float* cp = &g_cand[r * CAP];
#pragma unroll 1
            for (int b = 0; b < cnt; b += 4) {
                float v[4];
#pragma unroll
                for (int k = 0; k < 4; k++)
                    v[k] = (b + k < cnt) ? cp[b + k] : -FLT_MAX;
#pragma unroll
                for (int k = 0; k < 4; k++)
                    top10_insert(top, v[k]);
            }
            float sum_top = 0.0f;
#pragma unroll
            for (int k = 0; k < 10; k++) {
                float e = fmaxf(top[k] - 0.2f, 0.0f);
                sum_top += __expf(64.0f * e * e);
            }
            lse_n = logf(sum_top);
        } else if (nn > 0) {
            // exact fallback (never taken on this data): serial row scan
            const float* ss = sim + (size_t)r * N_COLS;
            const float* ll = lab + (size_t)r * N_COLS;
            float sum_n = 0.0f;
            float top[10];
#pragma unroll
            for (int k = 0; k < 10; k++) top[k] = -FLT_MAX;
            for (int i = 0; i < N_COLS; i++) {
                if (ll[i] < 0.25f) {
                    float s_ = ss[i];
                    float e = fmaxf(s_ - 0.2f, 0.0f);
                    sum_n += __expf(64.0f * e * e);
                    top10_insert(top, s_);
                }
            }
            if (nn > 20) {
                float sum_top = 0.0f;
#pragma unroll
                for (int k = 0; k < 10; k++) {
                    float e = fmaxf(top[k] - 0.2f, 0.0f);
                    sum_top += __expf(64.0f * e * e);
                }
                lse_n = logf(sum_top);
            } else {
                lse_n = logf(sum_n);
            }
        } else {
            lse_n = -FLT_MAX;               // no negatives: acts as -inf
        }

        float lse_p = (sp > 0.0f) ? logf(sp) : 0.0f;

        float x = lse_n + lse_p;
        float sploss;
        if (x > 0.0f) sploss = x + log1pf(expf(-x));
        else          sploss = log1pf(expf(x));

        // deterministic block-tree mean over 256 rows
        __shared__ float shf[B_ROWS / 32];
        float v = warpSumf(sploss);
        if (lane == 0) shf[wid] = v;
        __syncthreads();
        if (tid < 32) {
            float w = (tid < B_ROWS / 32) ? shf[tid] : 0.0f;
            w = warpSumf(w);
            if (tid == 0) {
                out[0] = w * (1.0f / (float)B_ROWS);
                g_done = 0;                 // reset for next graph replay
            }
        }
    }
}

extern "C" void kernel_launch(void* const* d_in, const int* in_sizes, int n_in,
                              void* d_out, int out_size)
{
    const float* sim = (const float*)d_in[0];
    const float* lab = (const float*)d_in[1];
    float* out = (float*)d_out;

    ranking_fused<<<NCHUNK, T1>>>(sim, lab, out);
}

// round 15
// speedup vs baseline: 1.5100x; 1.0571x over previous
#include <cuda_runtime.h>
#include <math.h>
#include <float.h>

#define B_ROWS 256
#define N_COLS 65536
#define SPLIT  4
#define CHUNK  (N_COLS / SPLIT)        // 16384 elements per CTA
#define T1     256                     // threads per pass-1 CTA
#define NCHUNK (B_ROWS * SPLIT)        // 1024 CTAs
#define CAP    256                     // candidate buffer per row
#define THRESH 0.998f                  // negative top-10 prefilter
#define NFCTA  32                      // finish kernel CTAs (8 rows each)

// Scratch (static device globals; no runtime allocation)
__device__ float g_sum_p[NCHUNK];
__device__ int   g_nneg[NCHUNK];
__device__ int   g_cnt[B_ROWS];        // zero-init; reset in finish each replay
__device__ float g_cand[B_ROWS * CAP];
__device__ float g_row_loss[B_ROWS];
__device__ int   g_done;               // zero-init; reset by elected finish CTA

__device__ __forceinline__ float warpSumf(float v) {
#pragma unroll
    for (int o = 16; o > 0; o >>= 1)
        v += __shfl_xor_sync(0xffffffffu, v, o);
    return v;
}
__device__ __forceinline__ int warpSumi(int v) {
#pragma unroll
    for (int o = 16; o > 0; o >>= 1)
        v += __shfl_xor_sync(0xffffffffu, v, o);
    return v;
}
__device__ __forceinline__ float warpMaxf(float v) {
#pragma unroll
    for (int o = 16; o > 0; o >>= 1)
        v = fmaxf(v, __shfl_xor_sync(0xffffffffu, v, o));
    return v;
}

// exp2 argument for positives: 92.33248*(0.8-sc)^2 expanded as quadratic in sc
// (92.33248 = 64*log2(e), so exp2(t) == exp(64*(0.8-sc)^2))
#define C_A  92.33248261689366f
#define C_B -147.73197218702986f
#define C_C  59.09278887481146f

__device__ __forceinline__ void process_elem(
    float s_, float l_,
    float& sum_p, float& s_min, float s_th,
    int& nneg, int* cnt_ptr, float* cand_ptr)
{
    // ---- positives: predicated exp with adaptive cutoff ----
    bool pos  = (l_ > 0.5f);
    bool keep = pos && (s_ < s_th);
    float sc = fminf(s_, 0.8f);
    float u  = fmaf(sc, C_A, C_B);
    float t  = fmaf(u, sc, C_C);            // = 92.332*(0.8-sc)^2
    if (keep) {
        sum_p += exp2f(t);                  // MUFU only when kept
        s_min  = fminf(s_min, s_);
    }

    // ---- negatives: count + rare candidate push (no per-elem top-10) ----
    bool neg = (l_ < 0.25f);
    nneg += neg;
    if (neg && (s_ > THRESH)) {             // ~1 hit per warp per kernel
        int idx = atomicAdd(cnt_ptr, 1);
        if (idx < CAP) cand_ptr[idx] = s_;
    }
}

// Sorted-ascending top-10 insert bubble (fallback path only)
__device__ __forceinline__ void top10_insert(float (&top)[10], float v) {
    if (v > top[0]) {
#pragma unroll
        for (int k = 0; k < 9; k++) {
            float hi = fmaxf(v, top[k]);
            top[k] = fminf(hi, top[k + 1]);
        }
        top[9] = fmaxf(v, top[9]);
    }
}

// ======================= pass 1: streaming (round-8 proven code) =============
__global__ __launch_bounds__(T1)
void ranking_pass1(const float* __restrict__ sim,
                   const float* __restrict__ lab)
{
    const int chunk = blockIdx.x;
    const int row   = chunk >> 2;           // SPLIT = 4
    const int part  = chunk & 3;
    const int tid   = threadIdx.x;
    const int lane  = tid & 31;
    const int wid   = tid >> 5;

    const size_t base = (size_t)row * N_COLS + (size_t)part * CHUNK;
    const float4* s4 = reinterpret_cast<const float4*>(sim + base);
    const float4* l4 = reinterpret_cast<const float4*>(lab + base);

    int*   cnt_ptr  = &g_cnt[row];
    float* cand_ptr = &g_cand[row * CAP];

    float sum_p = 0.0f;
    float s_min = FLT_MAX;
    float s_th  = FLT_MAX;
    int   nneg  = 0;

    // CHUNK/4 = 4096 float4s, 256 threads -> 16 float4 per thread.
    // 4 groups of 4 float4, threshold refresh between groups.
#pragma unroll 1
    for (int g = 0; g < 4; g++) {
#pragma unroll
        for (int j = 0; j < 4; j++) {
            int i = tid + (g * 4 + j) * T1;
            float4 s = s4[i];
            float4 l = l4[i];
            process_elem(s.x, l.x, sum_p, s_min, s_th, nneg, cnt_ptr, cand_ptr);
            process_elem(s.y, l.y, sum_p, s_min, s_th, nneg, cnt_ptr, cand_ptr);
            process_elem(s.z, l.z, sum_p, s_min, s_th, nneg, cnt_ptr, cand_ptr);
            process_elem(s.w, l.w, sum_p, s_min, s_th, nneg, cnt_ptr, cand_ptr);
        }
        // keep logit >= local_max_logit - 16:
        // max = 64*dmin^2 ; keep s <= 0.8 - sqrt(dmin^2 - 0.25)
        float dmin = 0.8f - s_min;
        s_th = (dmin <= 0.500001f) ? FLT_MAX
                                   : (0.8f - sqrtf(fmaf(dmin, dmin, -0.25f)));
    }

    // block reduction of sum_p / nneg
    __shared__ float sh_p[T1 / 32];
    __shared__ int   sh_n[T1 / 32];
    float wp = warpSumf(sum_p);
    int   wn = warpSumi(nneg);
    if (lane == 0) { sh_p[wid] = wp; sh_n[wid] = wn; }
    __syncthreads();
    if (tid < 32) {
        float p = (tid < T1 / 32) ? sh_p[tid] : 0.0f;
        int   n = (tid < T1 / 32) ? sh_n[tid] : 0;
        p = warpSumf(p);
        n = warpSumi(n);
        if (tid == 0) { g_sum_p[chunk] = p; g_nneg[chunk] = n; }
    }
}

// ============ pass 2: warp-per-row finisher (parallel candidate scan) ========
__global__ __launch_bounds__(256)
void ranking_finish(const float* __restrict__ sim,
                    const float* __restrict__ lab,
                    float* __restrict__ out)
{
    const int tid  = threadIdx.x;
    const int lane = tid & 31;
    const int wid  = tid >> 5;
    const int r    = blockIdx.x * 8 + wid;      // one warp per row

    // partial sums across the 4 chunks (lanes 0..3 load, warp-reduce)
    float sp = (lane < SPLIT) ? g_sum_p[r * SPLIT + lane] : 0.0f;
    int   nn = (lane < SPLIT) ? g_nneg[r * SPLIT + lane]  : 0;
    sp = warpSumf(sp);
    nn = warpSumi(nn);

    int cnt = g_cnt[r];                         // broadcast load (same addr)

    float lse_n;
    if (nn > 20 && cnt >= 10 && cnt <= CAP) {
        // fast path: all candidates loaded at once (MLP = cnt), exact top-10
        // by 10 rounds of warp-max extraction on the multiset.
        const float* cp = &g_cand[r * CAP];
        float v[CAP / 32];                      // 8 slots per lane
#pragma unroll
        for (int k = 0; k < CAP / 32; k++) {
            int idx = lane + k * 32;
            v[k] = (idx < cnt) ? cp[idx] : -FLT_MAX;
        }
        float sum_top = 0.0f;
#pragma unroll 1
        for (int rd = 0; rd < 10; rd++) {
            float m = v[0]; int am = 0;
#pragma unroll
            for (int k = 1; k < CAP / 32; k++)
                if (v[k] > m) { m = v[k]; am = k; }
            float wmax = warpMaxf(m);
            unsigned msk = __ballot_sync(0xffffffffu, m == wmax);
            int src = __ffs(msk) - 1;
            if (lane == src) {
#pragma unroll
                for (int k = 0; k < CAP / 32; k++)
                    if (k == am) v[k] = -FLT_MAX;
            }
            float e = fmaxf(wmax - 0.2f, 0.0f);
            sum_top += __expf(64.0f * e * e);   // replicated on all lanes
        }
        lse_n = logf(sum_top);
    } else if (nn > 0) {
        // exact fallback (never taken on this data): lane 0 serial row scan
        lse_n = -FLT_MAX;
        if (lane == 0) {
            const float* ss = sim + (size_t)r * N_COLS;
            const float* ll = lab + (size_t)r * N_COLS;
            float sum_n = 0.0f;
            float top[10];
#pragma unroll
            for (int k = 0; k < 10; k++) top[k] = -FLT_MAX;
            for (int i = 0; i < N_COLS; i++) {
                if (ll[i] < 0.25f) {
                    float s_ = ss[i];
                    float e = fmaxf(s_ - 0.2f, 0.0f);
                    sum_n += __expf(64.0f * e * e);
                    top10_insert(top, s_);
                }
            }
            if (nn > 20) {
                float sum_top = 0.0f;
#pragma unroll
                for (int k = 0; k < 10; k++) {
                    float e = fmaxf(top[k] - 0.2f, 0.0f);
                    sum_top += __expf(64.0f * e * e);
                }
                lse_n = logf(sum_top);
            } else {
                lse_n = logf(sum_n);
            }
        }
    } else {
        lse_n = -FLT_MAX;                       // no negatives: acts as -inf
    }

    if (lane == 0) {
        float lse_p = (sp > 0.0f) ? logf(sp) : 0.0f;
        float x = lse_n + lse_p;
        float sploss;
        if (x > 0.0f) sploss = x + log1pf(expf(-x));
        else          sploss = log1pf(expf(x));
        g_row_loss[r] = sploss;
        g_cnt[r] = 0;                           // reset for next graph replay
    }

    // ---- election among 32 small CTAs; elected sums 256 row losses ----
    __threadfence();
    __syncthreads();
    __shared__ int sh_elect;
    if (tid == 0)
        sh_elect = (atomicAdd(&g_done, 1) == (NFCTA - 1)) ? 1 : 0;
    __syncthreads();
    if (!sh_elect) return;

    __threadfence();                            // acquire other CTAs' row losses
    __shared__ float shf[8];
    float v = g_row_loss[tid];                  // 256 threads = 256 rows
    v = warpSumf(v);
    if (lane == 0) shf[wid] = v;
    __syncthreads();
    if (tid < 32) {
        float w = (tid < 8) ? shf[tid] : 0.0f;
        w = warpSumf(w);
        if (tid == 0) {
            out[0] = w * (1.0f / (float)B_ROWS);
            g_done = 0;                         // reset for next graph replay
        }
    }
}

extern "C" void kernel_launch(void* const* d_in, const int* in_sizes, int n_in,
                              void* d_out, int out_size)
{
    const float* sim = (const float*)d_in[0];
    const float* lab = (const float*)d_in[1];
    float* out = (float*)d_out;

    ranking_pass1<<<NCHUNK, T1>>>(sim, lab);
    ranking_finish<<<NFCTA, 256>>>(sim, lab, out);
}

// round 16
// speedup vs baseline: 1.5113x; 1.0009x over previous
#include <cuda_runtime.h>
#include <math.h>
#include <float.h>

#define B_ROWS 256
#define N_COLS 65536
#define SPLIT  4
#define CHUNK  (N_COLS / SPLIT)        // 16384 elements per CTA
#define T1     256                     // threads per CTA
#define NCHUNK (B_ROWS * SPLIT)        // 1024 CTAs (one wave at occ>=7)
#define CAP    256                     // candidate buffer per row
#define THRESH 0.998f                  // negative top-10 prefilter

// Scratch (static device globals; no runtime allocation)
__device__ float g_sum_p[NCHUNK];
__device__ int   g_nneg[NCHUNK];
__device__ int   g_cnt[B_ROWS];        // zero-init; reset by row-elected CTA
__device__ float g_cand[B_ROWS * CAP];
__device__ float g_row_loss[B_ROWS];
__device__ int   g_row_done[B_ROWS];   // zero-init; reset by row-elected CTA
__device__ int   g_done;               // zero-init; reset by final CTA

__device__ __forceinline__ float warpSumf(float v) {
#pragma unroll
    for (int o = 16; o > 0; o >>= 1)
        v += __shfl_xor_sync(0xffffffffu, v, o);
    return v;
}
__device__ __forceinline__ int warpSumi(int v) {
#pragma unroll
    for (int o = 16; o > 0; o >>= 1)
        v += __shfl_xor_sync(0xffffffffu, v, o);
    return v;
}
__device__ __forceinline__ float warpMaxf(float v) {
#pragma unroll
    for (int o = 16; o > 0; o >>= 1)
        v = fmaxf(v, __shfl_xor_sync(0xffffffffu, v, o));
    return v;
}

// exp2 argument for positives: 92.33248*(0.8-sc)^2 expanded as quadratic in sc
// (92.33248 = 64*log2(e), so exp2(t) == exp(64*(0.8-sc)^2))
#define C_A  92.33248261689366f
#define C_B -147.73197218702986f
#define C_C  59.09278887481146f

__device__ __forceinline__ void process_elem(
    float s_, float l_,
    float& sum_p, float& s_min, float s_th,
    int& nneg, int* cnt_ptr, float* cand_ptr)
{
    // ---- positives: predicated exp with adaptive cutoff ----
    bool pos  = (l_ > 0.5f);
    bool keep = pos && (s_ < s_th);
    float sc = fminf(s_, 0.8f);
    float u  = fmaf(sc, C_A, C_B);
    float t  = fmaf(u, sc, C_C);            // = 92.332*(0.8-sc)^2
    if (keep) {
        sum_p += exp2f(t);                  // MUFU only when kept
        s_min  = fminf(s_min, s_);
    }

    // ---- negatives: count + rare candidate push (no per-elem top-10) ----
    bool neg = (l_ < 0.25f);
    nneg += neg;
    if (neg && (s_ > THRESH)) {             // ~1 hit per warp per kernel
        int idx = atomicAdd(cnt_ptr, 1);
        if (idx < CAP) cand_ptr[idx] = s_;
    }
}

// Sorted-ascending top-10 insert bubble (fallback path only)
__device__ __forceinline__ void top10_insert(float (&top)[10], float v) {
    if (v > top[0]) {
#pragma unroll
        for (int k = 0; k < 9; k++) {
            float hi = fmaxf(v, top[k]);
            top[k] = fminf(hi, top[k + 1]);
        }
        top[9] = fmaxf(v, top[9]);
    }
}

__global__ __launch_bounds__(T1, 7)     // regs<=36: 1024 CTAs in ONE wave
void ranking_fused(const float* __restrict__ sim,
                   const float* __restrict__ lab,
                   float* __restrict__ out)
{
    const int chunk = blockIdx.x;
    const int row   = chunk >> 2;           // SPLIT = 4
    const int part  = chunk & 3;
    const int tid   = threadIdx.x;
    const int lane  = tid & 31;
    const int wid   = tid >> 5;

    const size_t base = (size_t)row * N_COLS + (size_t)part * CHUNK;
    const float4* s4 = reinterpret_cast<const float4*>(sim + base);
    const float4* l4 = reinterpret_cast<const float4*>(lab + base);

    int*   cnt_ptr  = &g_cnt[row];
    float* cand_ptr = &g_cand[row * CAP];

    float sum_p = 0.0f;
    float s_min = FLT_MAX;
    float s_th  = FLT_MAX;
    int   nneg  = 0;

    // CHUNK/4 = 4096 float4s, 256 threads -> 16 float4 per thread.
    // 4 groups of 4 float4 (proven-best shape), threshold refresh between.
#pragma unroll 1
    for (int g = 0; g < 4; g++) {
#pragma unroll
        for (int j = 0; j < 4; j++) {
            int i = tid + (g * 4 + j) * T1;
            float4 s = s4[i];
            float4 l = l4[i];
            process_elem(s.x, l.x, sum_p, s_min, s_th, nneg, cnt_ptr, cand_ptr);
            process_elem(s.y, l.y, sum_p, s_min, s_th, nneg, cnt_ptr, cand_ptr);
            process_elem(s.z, l.z, sum_p, s_min, s_th, nneg, cnt_ptr, cand_ptr);
            process_elem(s.w, l.w, sum_p, s_min, s_th, nneg, cnt_ptr, cand_ptr);
        }
        // keep logit >= local_max_logit - 16:
        // max = 64*dmin^2 ; keep s <= 0.8 - sqrt(dmin^2 - 0.25)
        float dmin = 0.8f - s_min;
        s_th = (dmin <= 0.500001f) ? FLT_MAX
                                   : (0.8f - sqrtf(fmaf(dmin, dmin, -0.25f)));
    }

    // ---- block reduction of sum_p / nneg, publish chunk partials ----
    __shared__ float sh_p[T1 / 32];
    __shared__ int   sh_n[T1 / 32];
    __shared__ int   sh_elect;
    float wp = warpSumf(sum_p);
    int   wn = warpSumi(nneg);
    if (lane == 0) { sh_p[wid] = wp; sh_n[wid] = wn; }
    __syncthreads();
    if (tid < 32) {
        float p = (tid < T1 / 32) ? sh_p[tid] : 0.0f;
        int   n = (tid < T1 / 32) ? sh_n[tid] : 0;
        p = warpSumf(p);
        n = warpSumi(n);
        if (tid == 0) { g_sum_p[chunk] = p; g_nneg[chunk] = n; }
    }

    // ---- per-row election: last of the row's 4 CTAs finishes the row ----
    __threadfence();                        // order partials + candidate pushes
    __syncthreads();
    if (tid == 0)
        sh_elect = (atomicAdd(&g_row_done[row], 1) == (SPLIT - 1)) ? 1 : 0;
    __syncthreads();
    if (!sh_elect) return;

    // This CTA finishes its row (overlaps with other rows still streaming).
    __threadfence();                        // acquire the row's other partials
    if (wid == 0) {
        float sp = (lane < SPLIT) ? g_sum_p[row * SPLIT + lane] : 0.0f;
        int   nn = (lane < SPLIT) ? g_nneg[row * SPLIT + lane]  : 0;
        sp = warpSumf(sp);
        nn = warpSumi(nn);

        int cnt = g_cnt[row];               // broadcast load

        float lse_n;
        if (nn > 20 && cnt >= 10 && cnt <= CAP) {
            // fast path: all candidates loaded at once, exact top-10 via
            // 10 rounds of warp-max extraction on the multiset.
            const float* cp = &g_cand[row * CAP];
            float v[CAP / 32];              // 8 slots per lane
#pragma unroll
            for (int k = 0; k < CAP / 32; k++) {
                int idx = lane + k * 32;
                v[k] = (idx < cnt) ? cp[idx] : -FLT_MAX;
            }
            float sum_top = 0.0f;
#pragma unroll 1
            for (int rd = 0; rd < 10; rd++) {
                float m = v[0]; int am = 0;
#pragma unroll
                for (int k = 1; k < CAP / 32; k++)
                    if (v[k] > m) { m = v[k]; am = k; }
                float wmax = warpMaxf(m);
                unsigned msk = __ballot_sync(0xffffffffu, m == wmax);
                int src = __ffs(msk) - 1;
                if (lane == src) {
#pragma unroll
                    for (int k = 0; k < CAP / 32; k++)
                        if (k == am) v[k] = -FLT_MAX;
                }
                float e = fmaxf(wmax - 0.2f, 0.0f);
                sum_top += __expf(64.0f * e * e);   // replicated on all lanes
            }
            lse_n = logf(sum_top);
        } else if (nn > 0) {
            // exact fallback (never taken on this data): lane 0 serial scan
            lse_n = -FLT_MAX;
            if (lane == 0) {
                const float* ss = sim + (size_t)row * N_COLS;
                const float* ll = lab + (size_t)row * N_COLS;
                float sum_n = 0.0f;
                float top[10];
#pragma unroll
                for (int k = 0; k < 10; k++) top[k] = -FLT_MAX;
                for (int i = 0; i < N_COLS; i++) {
                    if (ll[i] < 0.25f) {
                        float s_ = ss[i];
                        float e = fmaxf(s_ - 0.2f, 0.0f);
                        sum_n += __expf(64.0f * e * e);
                        top10_insert(top, s_);
                    }
                }
                if (nn > 20) {
                    float sum_top = 0.0f;
#pragma unroll
                    for (int k = 0; k < 10; k++) {
                        float e = fmaxf(top[k] - 0.2f, 0.0f);
                        sum_top += __expf(64.0f * e * e);
                    }
                    lse_n = logf(sum_top);
                } else {
                    lse_n = logf(sum_n);
                }
            }
        } else {
            lse_n = -FLT_MAX;               // no negatives: acts as -inf
        }

        if (lane == 0) {
            float lse_p = (sp > 0.0f) ? logf(sp) : 0.0f;
            float x = lse_n + lse_p;
            float sploss;
            if (x > 0.0f) sploss = x + log1pf(expf(-x));
            else          sploss = log1pf(expf(x));
            g_row_loss[row] = sploss;
            g_cnt[row]      = 0;            // reset for next graph replay
            g_row_done[row] = 0;            // reset for next graph replay
        }
    }

    // ---- global election among the 256 row-finishing CTAs ----
    __threadfence();                        // publish g_row_loss[row]
    __syncthreads();
    if (tid == 0)
        sh_elect = (atomicAdd(&g_done, 1) == (B_ROWS - 1)) ? 1 : 0;
    __syncthreads();
    if (!sh_elect) return;

    // final CTA: deterministic tree mean over 256 row losses
    __threadfence();                        // acquire all row losses
    {
        __shared__ float shf[T1 / 32];
        float v = g_row_loss[tid];          // T1 == B_ROWS
        v = warpSumf(v);
        if (lane == 0) shf[wid] = v;
        __syncthreads();
        if (tid < 32) {
            float w = (tid < T1 / 32) ? shf[tid] : 0.0f;
            w = warpSumf(w);
            if (tid == 0) {
                out[0] = w * (1.0f / (float)B_ROWS);
                g_done = 0;                 // reset for next graph replay
            }
        }
    }
}

extern "C" void kernel_launch(void* const* d_in, const int* in_sizes, int n_in,
                              void* d_out, int out_size)
{
    const float* sim = (const float*)d_in[0];
    const float* lab = (const float*)d_in[1];
    float* out = (float*)d_out;

    ranking_fused<<<NCHUNK, T1>>>(sim, lab, out);
}

// round 17
// speedup vs baseline: 1.5906x; 1.0525x over previous
#include <cuda_runtime.h>
#include <math.h>
#include <float.h>

#define B_ROWS 256
#define N_COLS 65536
#define SPLIT  4
#define CHUNK  (N_COLS / SPLIT)        // 16384 elements per CTA
#define T1     256                     // threads per CTA
#define NCHUNK (B_ROWS * SPLIT)        // 1024 CTAs (one wave)
#define CAP    256                     // candidate buffer per row
#define THRESH 0.998f                  // negative top-10 prefilter

// Scratch (static device globals; no runtime allocation)
__device__ float g_sum_p[NCHUNK];
__device__ int   g_nneg[NCHUNK];
__device__ int   g_cnt[B_ROWS];        // zero-init; reset by row-elected CTA
__device__ float g_cand[B_ROWS * CAP];
__device__ float g_row_loss[B_ROWS];
__device__ int   g_row_done[B_ROWS];   // zero-init; reset by row-elected CTA
__device__ int   g_done;               // zero-init; reset by final CTA

__device__ __forceinline__ float warpSumf(float v) {
#pragma unroll
    for (int o = 16; o > 0; o >>= 1)
        v += __shfl_xor_sync(0xffffffffu, v, o);
    return v;
}
__device__ __forceinline__ int warpSumi(int v) {
#pragma unroll
    for (int o = 16; o > 0; o >>= 1)
        v += __shfl_xor_sync(0xffffffffu, v, o);
    return v;
}
__device__ __forceinline__ float warpMaxf(float v) {
#pragma unroll
    for (int o = 16; o > 0; o >>= 1)
        v = fmaxf(v, __shfl_xor_sync(0xffffffffu, v, o));
    return v;
}

// acq_rel GPU-scope fetch-add: release (cumulatively, after __syncthreads)
// all this CTA's prior writes; acquire all releases it observes.
__device__ __forceinline__ int atomAddAcqRelGpu(int* p, int v) {
    int old;
    asm volatile("atom.add.acq_rel.gpu.global.s32 %0, [%1], %2;"
                 : "=r"(old) : "l"(p), "r"(v) : "memory");
    return old;
}

// exp2 argument for positives: 92.33248*(0.8-sc)^2 expanded as quadratic in sc
// (92.33248 = 64*log2(e), so exp2(t) == exp(64*(0.8-sc)^2))
#define C_A  92.33248261689366f
#define C_B -147.73197218702986f
#define C_C  59.09278887481146f

__device__ __forceinline__ void process_elem(
    float s_, float l_,
    float& sum_p, float& s_min, float s_th,
    int& nneg, int* cnt_ptr, float* cand_ptr)
{
    // ---- positives: predicated exp with adaptive cutoff ----
    bool pos  = (l_ > 0.5f);
    bool keep = pos && (s_ < s_th);
    float sc = fminf(s_, 0.8f);
    float u  = fmaf(sc, C_A, C_B);
    float t  = fmaf(u, sc, C_C);            // = 92.332*(0.8-sc)^2
    if (keep) {
        sum_p += exp2f(t);                  // MUFU only when kept
        s_min  = fminf(s_min, s_);
    }

    // ---- negatives: count + rare candidate push (no per-elem top-10) ----
    bool neg = (l_ < 0.25f);
    nneg += neg;
    if (neg && (s_ > THRESH)) {             // ~1 hit per warp per kernel
        int idx = atomicAdd(cnt_ptr, 1);
        if (idx < CAP) cand_ptr[idx] = s_;
    }
}

// Sorted-ascending top-10 insert bubble (fallback path only)
__device__ __forceinline__ void top10_insert(float (&top)[10], float v) {
    if (v > top[0]) {
#pragma unroll
        for (int k = 0; k < 9; k++) {
            float hi = fmaxf(v, top[k]);
            top[k] = fminf(hi, top[k + 1]);
        }
        top[9] = fmaxf(v, top[9]);
    }
}

__global__ __launch_bounds__(T1)
void ranking_fused(const float* __restrict__ sim,
                   const float* __restrict__ lab,
                   float* __restrict__ out)
{
    const int chunk = blockIdx.x;
    const int row   = chunk >> 2;           // SPLIT = 4
    const int part  = chunk & 3;
    const int tid   = threadIdx.x;
    const int lane  = tid & 31;
    const int wid   = tid >> 5;

    const size_t base = (size_t)row * N_COLS + (size_t)part * CHUNK;
    const float4* s4 = reinterpret_cast<const float4*>(sim + base);
    const float4* l4 = reinterpret_cast<const float4*>(lab + base);

    int*   cnt_ptr  = &g_cnt[row];
    float* cand_ptr = &g_cand[row * CAP];

    float sum_p = 0.0f;
    float s_min = FLT_MAX;
    float s_th  = FLT_MAX;
    int   nneg  = 0;

    // CHUNK/4 = 4096 float4s, 256 threads -> 16 float4 per thread.
    // 4 groups of 4 float4 (proven-best shape), threshold refresh between.
#pragma unroll 1
    for (int g = 0; g < 4; g++) {
#pragma unroll
        for (int j = 0; j < 4; j++) {
            int i = tid + (g * 4 + j) * T1;
            float4 s = s4[i];
            float4 l = l4[i];
            process_elem(s.x, l.x, sum_p, s_min, s_th, nneg, cnt_ptr, cand_ptr);
            process_elem(s.y, l.y, sum_p, s_min, s_th, nneg, cnt_ptr, cand_ptr);
            process_elem(s.z, l.z, sum_p, s_min, s_th, nneg, cnt_ptr, cand_ptr);
            process_elem(s.w, l.w, sum_p, s_min, s_th, nneg, cnt_ptr, cand_ptr);
        }
        // keep logit >= local_max_logit - 16:
        // max = 64*dmin^2 ; keep s <= 0.8 - sqrt(dmin^2 - 0.25)
        float dmin = 0.8f - s_min;
        s_th = (dmin <= 0.500001f) ? FLT_MAX
                                   : (0.8f - sqrtf(fmaf(dmin, dmin, -0.25f)));
    }

    // ---- block reduction of sum_p / nneg, publish chunk partials ----
    __shared__ float sh_p[T1 / 32];
    __shared__ int   sh_n[T1 / 32];
    __shared__ int   sh_elect;
    float wp = warpSumf(sum_p);
    int   wn = warpSumi(nneg);
    if (lane == 0) { sh_p[wid] = wp; sh_n[wid] = wn; }
    __syncthreads();
    if (tid < 32) {
        float p = (tid < T1 / 32) ? sh_p[tid] : 0.0f;
        int   n = (tid < T1 / 32) ? sh_n[tid] : 0;
        p = warpSumf(p);
        n = warpSumi(n);
        if (tid == 0) { g_sum_p[chunk] = p; g_nneg[chunk] = n; }
    }

    // ---- per-row election: last of the row's 4 CTAs finishes the row ----
    // __syncthreads (block acq_rel) + tid0 acq_rel atomic: by cumulativity
    // this releases ALL this CTA's prior writes and acquires the other
    // chunk-CTAs' released writes. No MEMBARs by the other 255 threads.
    __syncthreads();
    if (tid == 0)
        sh_elect = (atomAddAcqRelGpu(&g_row_done[row], 1) == (SPLIT - 1)) ? 1 : 0;
    __syncthreads();
    if (!sh_elect) return;

    // This CTA finishes its row (overlaps with other rows still streaming).
    if (wid == 0) {
        float sp = (lane < SPLIT) ? g_sum_p[row * SPLIT + lane] : 0.0f;
        int   nn = (lane < SPLIT) ? g_nneg[row * SPLIT + lane]  : 0;
        sp = warpSumf(sp);
        nn = warpSumi(nn);

        int cnt = g_cnt[row];               // broadcast load

        float lse_n;
        if (nn > 20 && cnt >= 10 && cnt <= CAP) {
            // fast path: all candidates loaded at once, exact top-10 via
            // 10 rounds of warp-max extraction on the multiset.
            const float* cp = &g_cand[row * CAP];
            float v[CAP / 32];              // 8 slots per lane
#pragma unroll
            for (int k = 0; k < CAP / 32; k++) {
                int idx = lane + k * 32;
                v[k] = (idx < cnt) ? cp[idx] : -FLT_MAX;
            }
            float sum_top = 0.0f;
#pragma unroll 1
            for (int rd = 0; rd < 10; rd++) {
                float m = v[0]; int am = 0;
#pragma unroll
                for (int k = 1; k < CAP / 32; k++)
                    if (v[k] > m) { m = v[k]; am = k; }
                float wmax = warpMaxf(m);
                unsigned msk = __ballot_sync(0xffffffffu, m == wmax);
                int src = __ffs(msk) - 1;
                if (lane == src) {
#pragma unroll
                    for (int k = 0; k < CAP / 32; k++)
                        if (k == am) v[k] = -FLT_MAX;
                }
                float e = fmaxf(wmax - 0.2f, 0.0f);
                sum_top += __expf(64.0f * e * e);   // replicated on all lanes
            }
            lse_n = logf(sum_top);
        } else if (nn > 0) {
            // exact fallback (never taken on this data): lane 0 serial scan
            lse_n = -FLT_MAX;
            if (lane == 0) {
                const float* ss = sim + (size_t)row * N_COLS;
                const float* ll = lab + (size_t)row * N_COLS;
                float sum_n = 0.0f;
                float top[10];
#pragma unroll
                for (int k = 0; k < 10; k++) top[k] = -FLT_MAX;
                for (int i = 0; i < N_COLS; i++) {
                    if (ll[i] < 0.25f) {
                        float s_ = ss[i];
                        float e = fmaxf(s_ - 0.2f, 0.0f);
                        sum_n += __expf(64.0f * e * e);
                        top10_insert(top, s_);
                    }
                }
                if (nn > 20) {
                    float sum_top = 0.0f;
#pragma unroll
                    for (int k = 0; k < 10; k++) {
                        float e = fmaxf(top[k] - 0.2f, 0.0f);
                        sum_top += __expf(64.0f * e * e);
                    }
                    lse_n = logf(sum_top);
                } else {
                    lse_n = logf(sum_n);
                }
            }
        } else {
            lse_n = -FLT_MAX;               // no negatives: acts as -inf
        }

        if (lane == 0) {
            float lse_p = (sp > 0.0f) ? logf(sp) : 0.0f;
            float x = lse_n + lse_p;
            float sploss;
            if (x > 0.0f) sploss = x + log1pf(expf(-x));
            else          sploss = log1pf(expf(x));
            g_row_loss[row] = sploss;
            g_cnt[row]      = 0;            // reset for next graph replay
            g_row_done[row] = 0;            // reset for next graph replay
        }
    }

    // ---- global election among the 256 row-finishing CTAs ----
    __syncthreads();
    if (tid == 0)
        sh_elect = (atomAddAcqRelGpu(&g_done, 1) == (B_ROWS - 1)) ? 1 : 0;
    __syncthreads();
    if (!sh_elect) return;

    // final CTA: deterministic tree mean over 256 row losses
    {
        __shared__ float shf[T1 / 32];
        float v = g_row_loss[tid];          // T1 == B_ROWS
        v = warpSumf(v);
        if (lane == 0) shf[wid] = v;
        __syncthreads();
        if (tid < 32) {
            float w = (tid < T1 / 32) ? shf[tid] : 0.0f;
            w = warpSumf(w);
            if (tid == 0) {
                out[0] = w * (1.0f / (float)B_ROWS);
                g_done = 0;                 // reset for next graph replay
            }
        }
    }
}

extern "C" void kernel_launch(void* const* d_in, const int* in_sizes, int n_in,
                              void* d_out, int out_size)
{
    const float* sim = (const float*)d_in[0];
    const float* lab = (const float*)d_in[1];
    float* out = (float*)d_out;

    ranking_fused<<<NCHUNK, T1>>>(sim, lab, out);
}